// round 16
// baseline (speedup 1.0000x reference)
#include <cuda_runtime.h>
#include <cuda.h>
#include <cstdint>
#include <cstring>

// Problem constants (fixed by the dataset)
#define NN 50000
#define NE 1600000
#define NT 50
#define FDT 0.02f

// Persistent-kernel geometry: 444 = 148 SMs * 3 blocks, co-resident at <=40 regs
#define PBLK 444
#define THREADS 512
#define GPB (THREADS / 4)           // 128 groups of 4 lanes per block (LDG kernel)
#define WPB 16                      // warps per block
#define ROWS_PW 8                   // rows per warp (TMA kernel): 444*16*8 = 56832 >= NN
#define CH 32                       // edges per TMA chunk (8 gather4s)
#define G4B 128                     // bytes per gather4 slot (64 data + 64 pad, 128B-aligned)
#define CHB ((CH / 4) * G4B)        // 1024 bytes per chunk buffer
#define CHUNK 113                   // ceil(NN / PBLK) for the grid scan
#define NBAR 64

// ---------------- device scratch (static, no allocations) ----------------
__device__ __align__(256) float g_r[2][NN * 4];  // rate tables, ping-pong, [node][batch]
__device__ float2 g_csr[NE];            // LDG path: {weight, bitcast(src)} CSR by target
__device__ float  g_w[NE];              // TMA path: weight per CSR slot
__device__ int    g_sidx[NE];           // TMA path: src node per CSR slot
__device__ int    g_pos[NE];            // per edge: slot within its target row
__device__ int    g_row_start[NN + 1];
__device__ int    g_deg[NN];
__device__ float  g_alpha[NN];
__device__ int    g_bars[NBAR];
__device__ int    g_part[PBLK];

// ---------------- init kernel (resets barrier state each graph replay) ----------
__global__ void init_kernel(const float* __restrict__ bias,
                            const float* __restrict__ tc) {
    int i = blockIdx.x * blockDim.x + threadIdx.x;
    if (i < NBAR) g_bars[i] = 0;
    if (i < NN) {
        g_deg[i] = 0;
        g_alpha[i] = FDT / fmaxf(tc[i], FDT);
        float rb = fmaxf(bias[i], 0.0f);
        *reinterpret_cast<float4*>(&g_r[0][4 * i]) = make_float4(rb, rb, rb, rb);
    }
}

// ---------------- barriers ----------------
__device__ __forceinline__ void full_barrier(int idx) {
    __threadfence();
    __syncthreads();
    if (threadIdx.x == 0) {
        atomicAdd(&g_bars[idx], 1);
        volatile int* p = &g_bars[idx];
        while (*p < PBLK) { __nanosleep(64); }
    }
    __syncthreads();
    __threadfence();
}

// Light barrier: no CCTL.IVALL so L1-resident edge data survives; all cross-step
// mutable data moves via L2 (st.cg/ld.cg or TMA-from-global).
__device__ __forceinline__ void light_barrier(int idx) {
    __syncthreads();
    if (threadIdx.x == 0) {
        int* a = &g_bars[idx];
        asm volatile("red.release.gpu.add.u32 [%0], 1;" :: "l"(a) : "memory");
        unsigned v;
        do {
            asm volatile("ld.relaxed.gpu.u32 %0, [%1];" : "=r"(v) : "l"(a));
            if (v < PBLK) __nanosleep(32);
        } while (v < PBLK);
        unsigned d;
        asm volatile("atom.acquire.gpu.add.u32 %0, [%1], 0;"
                     : "=r"(d) : "l"(a) : "memory");
    }
    __syncthreads();
}

// ---------------- shared prep (phases 1-3), parameterized on which arrays ----
__device__ __forceinline__ void do_prep(int bid, int tid, bool tma_layout,
                                        const int* __restrict__ src,
                                        const int* __restrict__ tgt,
                                        const float* __restrict__ sign,
                                        const float* __restrict__ cnt,
                                        const float* __restrict__ strg) {
    // phase 1: degree histogram (by target); atomic also yields slot
    for (int i = bid * THREADS + tid; i < NE; i += PBLK * THREADS)
        g_pos[i] = atomicAdd(&g_deg[tgt[i]], 1);
    full_barrier(0);

    // phase 2: grid-wide exclusive scan of g_deg
    {
        __shared__ int s_scan[THREADS];
        __shared__ int s_off;
        const int cbase = bid * CHUNK;
        int n = NN - cbase;
        if (n > CHUNK) n = CHUNK;
        if (n < 0) n = 0;
        int dval = (tid < n) ? g_deg[cbase + tid] : 0;
        s_scan[tid] = dval;
        __syncthreads();
        #pragma unroll
        for (int o = 1; o < THREADS; o <<= 1) {
            int v = (tid >= o) ? s_scan[tid - o] : 0;
            __syncthreads();
            s_scan[tid] += v;
            __syncthreads();
        }
        if (tid == 0) g_part[bid] = s_scan[THREADS - 1];
        full_barrier(1);
        {
            __shared__ int s_red[16];
            int acc = 0;
            for (int j = tid; j < bid; j += THREADS) acc += g_part[j];
            #pragma unroll
            for (int o = 16; o; o >>= 1) acc += __shfl_xor_sync(0xffffffffu, acc, o);
            if ((tid & 31) == 0) s_red[tid >> 5] = acc;
            __syncthreads();
            if (tid == 0) {
                int s = 0;
                #pragma unroll
                for (int w = 0; w < 16; w++) s += s_red[w];
                s_off = s;
            }
            __syncthreads();
        }
        if (tid < n) g_row_start[cbase + tid] = s_off + s_scan[tid] - dval;
        if (bid == PBLK - 1 && tid == 0) g_row_start[NN] = s_off + s_scan[THREADS - 1];
    }
    full_barrier(2);

    // phase 3: scatter edges into target-sorted CSR (atomic-free)
    for (int i = bid * THREADS + tid; i < NE; i += PBLK * THREADS) {
        float w = sign[i] * fmaxf(cnt[i], 0.0f) * fmaxf(strg[i], 0.0f);
        int slot = g_row_start[tgt[i]] + g_pos[i];
        if (tma_layout) {
            g_w[slot] = w;
            g_sidx[slot] = src[i];
        } else {
            g_csr[slot] = make_float2(w, __int_as_float(src[i]));
        }
    }
    full_barrier(3);
}

// ================= LDG fallback kernel (proven R13 engine) =================
__global__ void __launch_bounds__(THREADS, 3)
net_kernel(const float* __restrict__ bias,
           const float* __restrict__ x,
           float* __restrict__ out,
           const int* __restrict__ src, const int* __restrict__ tgt,
           const float* __restrict__ sign, const float* __restrict__ cnt,
           const float* __restrict__ strg) {
    const int tid = threadIdx.x;
    const int bid = blockIdx.x;
    do_prep(bid, tid, false, src, tgt, sign, cnt, strg);

    const int gid = bid * GPB + (tid >> 2);
    const int lig = tid & 3;
    const unsigned gmask = 0xFu << ((tid & 31) & ~3u);

    const bool ok = gid < NN;
    const int row = ok ? gid : 0;
    const int rs = ok ? g_row_start[row] : 0;
    const int re = ok ? g_row_start[row + 1] : 0;
    const float bi = ok ? __ldg(&bias[row]) : 0.0f;
    const float al = ok ? g_alpha[row] : 0.0f;
    float vb = bi;
    const float* xp = x + (size_t)lig * NT * NN + row;
    float*       op = out + (size_t)lig * NT * NN + row;

    for (int t = 0; t < NT; t++) {
        const float* __restrict__ rates = g_r[t & 1];
        float* __restrict__       rnew  = g_r[(t & 1) ^ 1];
        float xv = ok ? __ldcg(xp) : 0.0f;

        float ax = 0.f, ay = 0.f, az = 0.f, aw = 0.f;
        int i = rs + lig;
        for (; i + 4 < re; i += 8) {
            float2 p0 = g_csr[i];
            float2 p1 = g_csr[i + 4];
            float4 r0 = __ldcg(reinterpret_cast<const float4*>(
                                   rates + 4 * __float_as_int(p0.y)));
            float4 r1 = __ldcg(reinterpret_cast<const float4*>(
                                   rates + 4 * __float_as_int(p1.y)));
            ax = fmaf(r0.x, p0.x, ax); ay = fmaf(r0.y, p0.x, ay);
            az = fmaf(r0.z, p0.x, az); aw = fmaf(r0.w, p0.x, aw);
            ax = fmaf(r1.x, p1.x, ax); ay = fmaf(r1.y, p1.x, ay);
            az = fmaf(r1.z, p1.x, az); aw = fmaf(r1.w, p1.x, aw);
        }
        if (i < re) {
            float2 p0 = g_csr[i];
            float4 r0 = __ldcg(reinterpret_cast<const float4*>(
                                   rates + 4 * __float_as_int(p0.y)));
            ax = fmaf(r0.x, p0.x, ax); ay = fmaf(r0.y, p0.x, ay);
            az = fmaf(r0.z, p0.x, az); aw = fmaf(r0.w, p0.x, aw);
        }
        #pragma unroll
        for (int o = 2; o; o >>= 1) {
            ax += __shfl_xor_sync(gmask, ax, o, 4);
            ay += __shfl_xor_sync(gmask, ay, o, 4);
            az += __shfl_xor_sync(gmask, az, o, 4);
            aw += __shfl_xor_sync(gmask, aw, o, 4);
        }
        if (ok) {
            float sum = (lig == 0) ? ax : (lig == 1) ? ay : (lig == 2) ? az : aw;
            float vn = fmaf(al, bi - vb + sum + xv, vb);
            vb = vn;
            float rn = fmaxf(vn, 0.f);
            __stcg(&rnew[4 * row + lig], rn);
            __stcs(op, rn);
        }
        xp += NN;
        op += NN;
        if (t != NT - 1) light_barrier(4 + t);
    }
}

// ================= TMA gather4 kernel =================
__device__ __forceinline__ unsigned smem_u32(const void* p) {
    return (unsigned)__cvta_generic_to_shared(p);
}

__global__ void __launch_bounds__(THREADS, 3)
net_kernel_tma(const __grid_constant__ CUtensorMap tm0,
               const __grid_constant__ CUtensorMap tm1,
               const float* __restrict__ bias,
               const float* __restrict__ x,
               float* __restrict__ out,
               const int* __restrict__ src, const int* __restrict__ tgt,
               const float* __restrict__ sign, const float* __restrict__ cnt,
               const float* __restrict__ strg) {
    const int tid = threadIdx.x;
    const int bid = blockIdx.x;
    do_prep(bid, tid, true, src, tgt, sign, cnt, strg);

    // smem: per warp 2 chunk buffers of (CH/4) gather4 slots x 128B
    extern __shared__ __align__(1024) char dsm[];         // WPB * 2 * CHB bytes
    __shared__ alignas(8) unsigned long long s_mb[WPB][2];

    const int wid = tid >> 5;
    const int lane = tid & 31;
    const int lig = lane & 3;
    const unsigned gmask = 0xFu << (lane & ~3u);

    if (lane == 0) {
        asm volatile("mbarrier.init.shared.b64 [%0], 1;"
                     :: "r"(smem_u32(&s_mb[wid][0])) : "memory");
        asm volatile("mbarrier.init.shared.b64 [%0], 1;"
                     :: "r"(smem_u32(&s_mb[wid][1])) : "memory");
    }
    __syncthreads();

    const int gwarp = bid * WPB + wid;
    const int row0 = gwarp * ROWS_PW;
    const int row = row0 + (lane >> 2);
    const bool ok = row < NN;
    const int rs_l = ok ? g_row_start[row] : 0;
    const int re_l = ok ? g_row_start[row + 1] : 0;
    const int wr0 = (row0 < NN) ? row0 : NN;
    const int wr1 = (row0 + ROWS_PW < NN) ? row0 + ROWS_PW : NN;
    const int we_s = g_row_start[wr0];
    const int we_e = g_row_start[wr1];
    const int nch = (we_e - we_s + CH - 1) / CH;
    const float bi = ok ? __ldg(&bias[row]) : 0.0f;
    const float al = ok ? g_alpha[row] : 0.0f;
    float vb = bi;
    int ph0 = 0, ph1 = 0;

    const char* wbuf = dsm + wid * (2 * CHB);
    const unsigned wbuf_a = smem_u32(wbuf);
    const unsigned mb_a0 = smem_u32(&s_mb[wid][0]);
    const unsigned mb_a1 = smem_u32(&s_mb[wid][1]);

    const float* xp = x + (size_t)lig * NT * NN + (ok ? row : 0);
    float*       op = out + (size_t)lig * NT * NN + (ok ? row : 0);

    for (int t = 0; t < NT; t++) {
        const CUtensorMap* tmp_ = (t & 1) ? &tm1 : &tm0;
        float* __restrict__ rnew = g_r[(t & 1) ^ 1];
        float xv = ok ? __ldcg(xp) : 0.0f;

        float ax = 0.f, ay = 0.f, az = 0.f, aw = 0.f;

        // issue chunk 0
        if (lane == 0 && nch > 0) {
            int cs = we_s, ce = (cs + CH < we_e) ? cs + CH : we_e;
            int ng = (ce - cs + 3) >> 2;
            asm volatile("mbarrier.arrive.expect_tx.shared.b64 _, [%0], %1;"
                         :: "r"(mb_a0), "r"((unsigned)(ng * 64)) : "memory");
            for (int k = 0; k < ng; k++) {
                int e = cs + 4 * k;
                int y0 = g_sidx[e];
                int y1 = (e + 1 < we_e) ? g_sidx[e + 1] : 0;
                int y2 = (e + 2 < we_e) ? g_sidx[e + 2] : 0;
                int y3 = (e + 3 < we_e) ? g_sidx[e + 3] : 0;
                asm volatile(
                    "cp.async.bulk.tensor.2d.tile::gather4.shared::cta.global"
                    ".mbarrier::complete_tx::bytes [%0], [%1, {%2, %3, %4, %5, %6}], [%7];"
                    :: "r"(wbuf_a + k * G4B), "l"(tmp_), "r"(0),
                       "r"(y0), "r"(y1), "r"(y2), "r"(y3), "r"(mb_a0) : "memory");
            }
        }

        for (int c = 0; c < nch; c++) {
            // issue chunk c+1 into the other buffer
            if (lane == 0 && c + 1 < nch) {
                int cs1 = we_s + (c + 1) * CH;
                int ce1 = (cs1 + CH < we_e) ? cs1 + CH : we_e;
                int ng = (ce1 - cs1 + 3) >> 2;
                unsigned mb = ((c + 1) & 1) ? mb_a1 : mb_a0;
                unsigned db = wbuf_a + ((c + 1) & 1) * CHB;
                asm volatile("mbarrier.arrive.expect_tx.shared.b64 _, [%0], %1;"
                             :: "r"(mb), "r"((unsigned)(ng * 64)) : "memory");
                for (int k = 0; k < ng; k++) {
                    int e = cs1 + 4 * k;
                    int y0 = g_sidx[e];
                    int y1 = (e + 1 < we_e) ? g_sidx[e + 1] : 0;
                    int y2 = (e + 2 < we_e) ? g_sidx[e + 2] : 0;
                    int y3 = (e + 3 < we_e) ? g_sidx[e + 3] : 0;
                    asm volatile(
                        "cp.async.bulk.tensor.2d.tile::gather4.shared::cta.global"
                        ".mbarrier::complete_tx::bytes [%0], [%1, {%2, %3, %4, %5, %6}], [%7];"
                        :: "r"(db + k * G4B), "l"(tmp_), "r"(0),
                           "r"(y0), "r"(y1), "r"(y2), "r"(y3), "r"(mb) : "memory");
                }
            }
            // wait for chunk c (lane 0), then broadcast via syncwarp
            const int b = c & 1;
            if (lane == 0) {
                unsigned mb = b ? mb_a1 : mb_a0;
                unsigned phw = (unsigned)(b ? ph1 : ph0);
                asm volatile(
                    "{\n\t.reg .pred P;\n\t"
                    "WL%=:\n\t"
                    "mbarrier.try_wait.parity.acquire.cta.shared::cta.b64 P, [%0], %1, 0x989680;\n\t"
                    "@!P bra WL%=;\n\t}"
                    :: "r"(mb), "r"(phw) : "memory");
            }
            __syncwarp();
            if (b) ph1 ^= 1; else ph0 ^= 1;

            // consume chunk c: edge e at slot (e_rel>>2)*128 + (e_rel&3)*16
            const int cs = we_s + c * CH;
            const int ce = (cs + CH < we_e) ? cs + CH : we_e;
            const char* bufp = wbuf + b * CHB;
            int i0 = rs_l + lig;
            if (i0 < cs) i0 += (((cs - i0) + 3) >> 2) << 2;
            const int hi = (re_l < ce) ? re_l : ce;
            for (int i = i0; i < hi; i += 4) {
                float w = g_w[i];
                int er = i - cs;
                const float4 r = *reinterpret_cast<const float4*>(
                    bufp + (er >> 2) * G4B + (er & 3) * 16);
                ax = fmaf(r.x, w, ax);
                ay = fmaf(r.y, w, ay);
                az = fmaf(r.z, w, az);
                aw = fmaf(r.w, w, aw);
            }
            __syncwarp();              // all lanes done with buffer b before reissue
        }

        #pragma unroll
        for (int o = 2; o; o >>= 1) {
            ax += __shfl_xor_sync(gmask, ax, o, 4);
            ay += __shfl_xor_sync(gmask, ay, o, 4);
            az += __shfl_xor_sync(gmask, az, o, 4);
            aw += __shfl_xor_sync(gmask, aw, o, 4);
        }
        if (ok) {
            float sum = (lig == 0) ? ax : (lig == 1) ? ay : (lig == 2) ? az : aw;
            float vn = fmaf(al, bi - vb + sum + xv, vb);
            vb = vn;
            float rn = fmaxf(vn, 0.f);
            __stcg(&rnew[4 * row + lig], rn);
            __stcs(op, rn);
        }
        xp += NN;
        op += NN;

        if (t != NT - 1) {
            asm volatile("fence.proxy.async;" ::: "memory");  // st.cg -> TMA reads
            light_barrier(4 + t);
        }
    }
}

// ---------------- host: tensormap setup + launch ----------------
typedef CUresult (*EncodeFn)(CUtensorMap*, CUtensorMapDataType, cuuint32_t, void*,
                             const cuuint64_t*, const cuuint64_t*, const cuuint32_t*,
                             const cuuint32_t*, CUtensorMapInterleave, CUtensorMapSwizzle,
                             CUtensorMapL2promotion, CUtensorMapFloatOOBfill);

static bool build_map(EncodeFn fn, CUtensorMap* tm, void* base) {
    cuuint64_t dims[2] = {4, NN};
    cuuint64_t strides[1] = {16};
    cuuint32_t estr[2] = {1, 1};
    cuuint32_t box1[2] = {4, 1};
    if (fn(tm, CU_TENSOR_MAP_DATA_TYPE_FLOAT32, 2, base, dims, strides, box1, estr,
           CU_TENSOR_MAP_INTERLEAVE_NONE, CU_TENSOR_MAP_SWIZZLE_NONE,
           CU_TENSOR_MAP_L2_PROMOTION_L2_128B,
           CU_TENSOR_MAP_FLOAT_OOB_FILL_NONE) == CUDA_SUCCESS)
        return true;
    cuuint32_t box4[2] = {4, 4};
    return fn(tm, CU_TENSOR_MAP_DATA_TYPE_FLOAT32, 2, base, dims, strides, box4, estr,
              CU_TENSOR_MAP_INTERLEAVE_NONE, CU_TENSOR_MAP_SWIZZLE_NONE,
              CU_TENSOR_MAP_L2_PROMOTION_L2_128B,
              CU_TENSOR_MAP_FLOAT_OOB_FILL_NONE) == CUDA_SUCCESS;
}

extern "C" void kernel_launch(void* const* d_in, const int* in_sizes, int n_in,
                              void* d_out, int out_size) {
    const float* x      = (const float*)d_in[0];  // [B,T,N]
    const float* bias   = (const float*)d_in[1];  // [N]
    const float* tcst   = (const float*)d_in[2];  // [N]
    const float* sign   = (const float*)d_in[3];  // [E]
    const float* cnt    = (const float*)d_in[4];  // [E]
    const float* strg   = (const float*)d_in[5];  // [E]
    const int*   srcidx = (const int*)d_in[6];    // [E]
    const int*   tgtidx = (const int*)d_in[7];    // [E]
    float* out = (float*)d_out;                   // [B,T,N]

    // Try to set up the TMA gather4 path (host-only queries; graph-capture safe).
    static CUtensorMap tm0, tm1;
    bool use_tma = false;
    {
        EncodeFn fn = nullptr;
#if CUDART_VERSION >= 12050
        cudaDriverEntryPointQueryResult qr;
        if (cudaGetDriverEntryPointByVersion("cuTensorMapEncodeTiled", (void**)&fn,
                                             12000, cudaEnableDefault, &qr)
                != cudaSuccess)
            fn = nullptr;
#else
        cudaDriverEntryPointQueryResult qr;
        if (cudaGetDriverEntryPoint("cuTensorMapEncodeTiled", (void**)&fn,
                                    cudaEnableDefault, &qr) != cudaSuccess)
            fn = nullptr;
#endif
        void* rbase = nullptr;
        if (fn && cudaGetSymbolAddress(&rbase, g_r) == cudaSuccess && rbase) {
            char* b = (char*)rbase;
            if (build_map(fn, &tm0, b) &&
                build_map(fn, &tm1, b + (size_t)NN * 4 * sizeof(float)))
                use_tma = true;
        }
    }

    const int nblk = (NN + 255) / 256;
    init_kernel<<<nblk, 256>>>(bias, tcst);
    if (use_tma) {
        const int smem = WPB * 2 * CHB;       // 32 KB
        net_kernel_tma<<<PBLK, THREADS, smem>>>(tm0, tm1, bias, x, out,
                                                srcidx, tgtidx, sign, cnt, strg);
    } else {
        net_kernel<<<PBLK, THREADS>>>(bias, x, out, srcidx, tgtidx, sign, cnt, strg);
    }

    (void)in_sizes; (void)n_in; (void)out_size;
}